// round 7
// baseline (speedup 1.0000x reference)
#include <cuda_runtime.h>
#include <cuda_bf16.h>
#include <cstdint>

#define CC 256
#define HH 128
#define WW 128
#define HWSZ (HH*WW)
#define WKP_W 132                  // wk pitch in words (264 bf16)
#define XBP   264                  // xbw pitch in words per c2 row
#define STGP  264                  // stage pitch in floats
#define STG_BUF 4224               // words per stage buffer (16*264)

// shared layout in 4-byte units
#define SM_WK   0                          // [64][132] words  = 8448
#define SM_STG  8448                       // 2 x [16][264] fp32 = 8448
#define SM_XBW  16896                      // [8][264] words = 2112
#define SM_KQS  19008                      // [2 grp][256 pix][4 s] = 2048
#define SM_WBUF 21056                      // [16 win][68] = 1088
#define SMEM_WORDS 22144
#define SMEM_BYTES (SMEM_WORDS*4)          // 88576

__device__ __forceinline__ unsigned pack_bf2(float lo, float hi) {
    __nv_bfloat162 h = __floats2bfloat162_rn(lo, hi);
    return *reinterpret_cast<unsigned*>(&h);
}

__global__ __launch_bounds__(512, 2) void frac_fused_kernel(
    const float* __restrict__ x,
    const float* __restrict__ w_key,
    const float* __restrict__ w_sim,
    float* __restrict__ out)
{
    extern __shared__ float S[];
    unsigned* wkw  = (unsigned*)(S + SM_WK);        // [key][132] words
    unsigned* xbw  = (unsigned*)(S + SM_XBW);       // [c2][264] words
    float*    kqs  = S + SM_KQS;                    // [grp][pix][s]
    float*    wbuf = S + SM_WBUF;                   // [win][16p][4s] pitch 68

    const int tid  = threadIdx.x;
    const int wp   = tid >> 5;
    const int lane = tid & 31;
    const int gid  = lane >> 2;        // 0..7
    const int ctid = lane & 3;         // 0..3
    const int grpM = wp & 1;           // 2 m-groups
    const int mtb  = grpM * 32;        // key-row tile base (rows mtb..mtb+31)
    const int pixb = (wp >> 1) * 32;   // pixel tile base (8 groups of 32)
    const int wh = blockIdx.x;         // 0..1
    const int hh = blockIdx.y;         // 0..31
    const int n  = blockIdx.z;         // 0..15

    const float* xpix = x + ((size_t)n*CC)*HWSZ + (size_t)(hh*4)*WW + wh*64;
    const uint32_t sbase = (uint32_t)__cvta_generic_to_shared(S);

    // ---- prefetch chunks 0 and 1 via cp.async ----
    #pragma unroll
    for (int pc = 0; pc < 2; pc++) {
        #pragma unroll
        for (int i = 0; i < 2; i++) {
            int id = i*512 + tid;              // 0..1023: c(16) x p4(64)
            int c = id >> 6, p4 = id & 63;
            const float* g = xpix + (size_t)(pc*16 + c)*HWSZ + (p4 >> 4)*WW + (p4 & 15)*4;
            uint32_t d = sbase + (uint32_t)((SM_STG + pc*STG_BUF + c*STGP + p4*4) * 4);
            asm volatile("cp.async.ca.shared.global [%0], [%1], 16;" :: "r"(d), "l"(g));
        }
        asm volatile("cp.async.commit_group;");
    }

    // ---- prologue: w_key -> bf16 smem [key][k] ----
    for (int i = tid; i < 64*128; i += 512) {
        int k = i >> 7, c2 = i & 127;
        float2 v = *(const float2*)(w_key + k*256 + c2*2);
        wkw[k*WKP_W + c2] = pack_bf2(v.x, v.y);
    }

    // per-lane ldmatrix address for A (row = key, 16B col-half)
    const uint32_t a_lane_addr = sbase + (uint32_t)(SM_WK*4)
        + (uint32_t)(((mtb + (lane & 15)) * (WKP_W*2) + (lane >> 4) * 8) * 2);

    float acc[2][4][4];
    #pragma unroll
    for (int t = 0; t < 2; t++)
        #pragma unroll
        for (int i = 0; i < 4; i++)
            #pragma unroll
            for (int j = 0; j < 4; j++) acc[t][i][j] = 0.f;

    for (int ch = 0; ch < 16; ch++) {
        if (ch < 15) { asm volatile("cp.async.wait_group 1;"); }
        else         { asm volatile("cp.async.wait_group 0;"); }
        __syncthreads();                       // stage(ch) visible; prev GEMM xbw reads done

        // ---- convert stage(ch) fp32 -> bf16 c-interleaved xbw ----
        {
            const float* stg = S + SM_STG + (ch & 1)*STG_BUF;
            int c2 = tid >> 6, q = tid & 63;   // one uint4 per thread
            float4 fa = *(const float4*)(stg + (2*c2  )*STGP + q*4);
            float4 fb = *(const float4*)(stg + (2*c2+1)*STGP + q*4);
            uint4 wv;
            wv.x = pack_bf2(fa.x, fb.x);
            wv.y = pack_bf2(fa.y, fb.y);
            wv.z = pack_bf2(fa.z, fb.z);
            wv.w = pack_bf2(fa.w, fb.w);
            *(uint4*)(xbw + c2*XBP + q*4) = wv;
        }
        __syncthreads();                       // xbw ready; stage(ch) drained

        // ---- issue prefetch for chunk ch+2 into freed buffer ----
        if (ch < 14) {
            #pragma unroll
            for (int i = 0; i < 2; i++) {
                int id = i*512 + tid;
                int c = id >> 6, p4 = id & 63;
                const float* g = xpix + (size_t)((ch+2)*16 + c)*HWSZ + (p4 >> 4)*WW + (p4 & 15)*4;
                uint32_t d = sbase + (uint32_t)((SM_STG + (ch & 1)*STG_BUF + c*STGP + p4*4) * 4);
                asm volatile("cp.async.ca.shared.global [%0], [%1], 16;" :: "r"(d), "l"(g));
            }
            asm volatile("cp.async.commit_group;");
        }

        // ---- GEMM step: one k16 slab; warp tile M=32, N=32 ----
        #pragma unroll
        for (int t = 0; t < 2; t++) {
            unsigned a0, a1, a2, a3;
            asm volatile(
                "ldmatrix.sync.aligned.m8n8.x4.shared.b16 {%0,%1,%2,%3}, [%4];"
                : "=r"(a0), "=r"(a1), "=r"(a2), "=r"(a3)
                : "r"(a_lane_addr + (unsigned)(t*16*WKP_W*4 + ch*32)));
            #pragma unroll
            for (int nt = 0; nt < 4; nt++) {
                int pix = pixb + nt*8 + gid;
                unsigned b0 = xbw[ctid*XBP + pix];
                unsigned b1 = xbw[(ctid + 4)*XBP + pix];
                asm volatile(
                    "mma.sync.aligned.m16n8k16.row.col.f32.bf16.bf16.f32 "
                    "{%0,%1,%2,%3}, {%4,%5,%6,%7}, {%8,%9}, {%0,%1,%2,%3};"
                    : "+f"(acc[t][nt][0]), "+f"(acc[t][nt][1]),
                      "+f"(acc[t][nt][2]), "+f"(acc[t][nt][3])
                    : "r"(a0), "r"(a1), "r"(a2), "r"(a3), "r"(b0), "r"(b1));
            }
        }
    }

    // ---- epilogue kq: relu + w_sim contraction from accumulators ----
    // lane's 4 key rows: mtb+gid + {0, 8, 16, 24}  (ridx = t*2 + half)
    float ws[4][4];
    #pragma unroll
    for (int s = 0; s < 4; s++) {
        ws[0][s] = w_sim[s*64 + mtb + gid];
        ws[1][s] = w_sim[s*64 + mtb + gid + 8];
        ws[2][s] = w_sim[s*64 + mtb + gid + 16];
        ws[3][s] = w_sim[s*64 + mtb + gid + 24];
    }
    #pragma unroll
    for (int nt = 0; nt < 4; nt++) {
        float part[2][4];
        #pragma unroll
        for (int u = 0; u < 2; u++) {
            float v0 = fmaxf(acc[0][nt][u],     0.f);   // row mtb+gid
            float v1 = fmaxf(acc[0][nt][2 + u], 0.f);   // +8
            float v2 = fmaxf(acc[1][nt][u],     0.f);   // +16
            float v3 = fmaxf(acc[1][nt][2 + u], 0.f);   // +24
            #pragma unroll
            for (int s = 0; s < 4; s++)
                part[u][s] = ws[0][s]*v0 + ws[1][s]*v1 + ws[2][s]*v2 + ws[3][s]*v3;
        }
        #pragma unroll
        for (int off = 4; off <= 16; off <<= 1)
            #pragma unroll
            for (int u = 0; u < 2; u++)
                #pragma unroll
                for (int s = 0; s < 4; s++)
                    part[u][s] += __shfl_xor_sync(0xffffffffu, part[u][s], off);
        if (gid == 0) {
            #pragma unroll
            for (int u = 0; u < 2; u++) {
                int pix = pixb + nt*8 + 2*ctid + u;
                *(float4*)(kqs + grpM*1024 + pix*4) = make_float4(
                    part[u][0], part[u][1], part[u][2], part[u][3]);
            }
        }
    }
    __syncthreads();                           // kqs complete

    // ---- per-window softmax (16 windows x 4 s = 64 threads) ----
    if (tid < 64) {
        int win = tid >> 2, s = tid & 3;
        float v[16], m = -1e30f;
        #pragma unroll
        for (int r0 = 0; r0 < 4; r0++)
            #pragma unroll
            for (int j = 0; j < 4; j++) {
                int pix = r0*64 + win*4 + j;
                float t = (kqs[pix*4 + s] + kqs[1024 + pix*4 + s]) * 0.25f;
                v[r0*4+j] = t;
                m = fmaxf(m, t);
            }
        float sum = 0.f;
        #pragma unroll
        for (int p = 0; p < 16; p++) { float e = __expf(v[p]-m); v[p] = e; sum += e; }
        float inv = 1.f / sum;
        #pragma unroll
        for (int p = 0; p < 16; p++) wbuf[win*68 + p*4 + s] = v[p]*inv;
    }
    __syncthreads();                           // wbuf ready

    // ---- aggregation: lane = (win,sp); warp strides channels ----
    {
        const int sp  = tid & 1;
        const int win = (tid >> 1) & 15;
        float2 w2[16];
        #pragma unroll
        for (int p = 0; p < 16; p++)
            w2[p] = *(const float2*)(wbuf + win*68 + p*4 + 2*sp);
        const int ww = wh*16 + win;
        const float* gw = xpix + win*4;
        #pragma unroll 4
        for (int it = 0; it < 16; it++) {
            int c = it*16 + wp;
            const float* xc = gw + (size_t)c*HWSZ;
            float o0 = 0.f, o1 = 0.f;
            #pragma unroll
            for (int r0 = 0; r0 < 4; r0++) {
                float4 xv = *(const float4*)(xc + r0*WW);
                o0 += xv.x*w2[r0*4+0].x + xv.y*w2[r0*4+1].x
                    + xv.z*w2[r0*4+2].x + xv.w*w2[r0*4+3].x;
                o1 += xv.x*w2[r0*4+0].y + xv.y*w2[r0*4+1].y
                    + xv.z*w2[r0*4+2].y + xv.w*w2[r0*4+3].y;
            }
            float2* op = (float2*)(out + ((size_t)(n*CC + c)*64 + (2*hh+sp))*64 + 2*ww);
            *op = make_float2(o0, o1);
        }
    }
}

extern "C" void kernel_launch(void* const* d_in, const int* in_sizes, int n_in,
                              void* d_out, int out_size)
{
    (void)in_sizes; (void)n_in; (void)out_size;
    const float* x  = (const float*)d_in[0];
    const float* wk = (const float*)d_in[1];
    const float* ws = (const float*)d_in[2];
    float* out = (float*)d_out;

    cudaFuncSetAttribute(frac_fused_kernel,
                         cudaFuncAttributeMaxDynamicSharedMemorySize, SMEM_BYTES);
    frac_fused_kernel<<<dim3(2, 32, 16), 512, SMEM_BYTES>>>(x, wk, ws, out);
}